// round 2
// baseline (speedup 1.0000x reference)
#include <cuda_runtime.h>
#include <cstdint>

// VectorQuantizer — bit-replication of the JAX reference numerics.
//   dist_k = fl( fl(||z||^2 + ||e_k||^2) - 2 * C_k ),  C_k = ascending-d FFMA dot
//   argmin with first-index tie-break; Zq_out = fl(z + fl(e - z)); loss = 1.25*mean((e-z)^2)

typedef unsigned long long u64;

#define DDIM 64
#define KC 512
#define KHALF 256
#define HW 4096
#define CHW 262144
#define NVEC 131072
#define THREADS 256
#define NBLOCKS 256          // NVEC / (THREADS * 2 vectors/thread)
#define ZQ_ELEMS 8388608
#define KSTRIDE 258          // u64 row stride for Edup (staging bank relief, 16B-aligned)

__device__ float g_blocksums[NBLOCKS];

__device__ __forceinline__ u64 fma2(u64 a, u64 b, u64 c) {
    u64 d; asm("fma.rn.f32x2 %0,%1,%2,%3;" : "=l"(d) : "l"(a), "l"(b), "l"(c)); return d;
}
__device__ __forceinline__ u64 pack2(float lo, float hi) {
    u64 d; asm("mov.b64 %0,{%1,%2};" : "=l"(d) : "f"(lo), "f"(hi)); return d;
}
__device__ __forceinline__ void unpack2(u64 a, float& lo, float& hi) {
    asm("mov.b64 {%0,%1},%2;" : "=f"(lo), "=f"(hi) : "l"(a));
}
__device__ __forceinline__ void lds_v2u64(u64& a, u64& b, uint32_t addr) {
    asm volatile("ld.shared.v2.u64 {%0,%1},[%2];" : "=l"(a), "=l"(b) : "r"(addr));
}

__global__ void __launch_bounds__(THREADS, 1)
vq_main_kernel(const float* __restrict__ inp, const float* __restrict__ E,
               float* __restrict__ out, int zq_off)
{
    extern __shared__ u64 sm[];            // Edup: [64][KSTRIDE] u64, (e,e) pairs
    float* Bsh = (float*)(sm + DDIM * KSTRIDE);   // ||e_k||^2, 512 floats
    __shared__ float red[8];

    const int tid = threadIdx.x;
    uint32_t sE = (uint32_t)__cvta_generic_to_shared(sm);

    // --- B_k = sum_d fl(e^2), ascending d (matches XLA mul-then-reduce) ---
    for (int k = tid; k < KC; k += THREADS) {
        const float* er = E + k * DDIM;
        float bsum = 0.f;
        #pragma unroll
        for (int d = 0; d < DDIM; d++) { float e = er[d]; float sq = e * e; bsum = bsum + sq; }
        Bsh[k] = bsum;
    }

    // --- load the two vectors (lane-lo = n0 in first half, lane-hi = n1 in second half) ---
    const int n0 = blockIdx.x * THREADS + tid;
    const int n1 = n0 + (NVEC / 2);
    const int b0 = n0 >> 12, hw0 = n0 & 4095;
    const int b1 = n1 >> 12, hw1 = n1 & 4095;
    const float* z0p = inp + (size_t)b0 * CHW + hw0;
    const float* z1p = inp + (size_t)b1 * CHW + hw1;

    u64 zp[DDIM];
    float A0 = 0.f, A1 = 0.f;   // ||z||^2 (order-insensitive: grid-shift commutes)
    #pragma unroll
    for (int d = 0; d < DDIM; d++) {
        float a = __ldg(z0p + (size_t)d * HW);
        float c = __ldg(z1p + (size_t)d * HW);
        float sa = a * a, sc = c * c;
        A0 = A0 + sa; A1 = A1 + sc;
        zp[d] = pack2(a, c);
    }

    float best0 = 3.402823466e38f, best1 = 3.402823466e38f;
    int bi0 = 0, bi1 = 0;

    for (int pass = 0; pass < 2; pass++) {
        const int k0 = pass * KHALF;
        __syncthreads();   // previous pass readers done before restaging
        // stage Edup: coalesced global reads (d fast), duplicated lanes
        for (int idx = tid; idx < KHALF * DDIM; idx += THREADS) {
            int k = idx >> 6, d = idx & 63;
            float e = __ldg(E + (k0 + k) * DDIM + d);
            sm[(size_t)d * KSTRIDE + k] = pack2(e, e);
        }
        __syncthreads();

        for (int kp = 0; kp < KHALF; kp += 2) {
            u64 acc_a = 0ull, acc_b = 0ull;           // chains start at 0 (cublas-style)
            uint32_t base = sE + (uint32_t)kp * 8;
            #pragma unroll
            for (int d = 0; d < DDIM; d++) {          // ascending d, single FFMA chain/lane
                u64 ea, eb;
                lds_v2u64(ea, eb, base + d * (KSTRIDE * 8));
                acc_a = fma2(zp[d], ea, acc_a);
                acc_b = fma2(zp[d], eb, acc_b);
            }
            float ca0, ca1, cb0, cb1;
            unpack2(acc_a, ca0, ca1);
            unpack2(acc_b, cb0, cb1);
            const float Ba = Bsh[kp + k0 - k0 + kp == kp ? (k0 + kp) : (k0 + kp)]; // (see below)
            const float Bb = Bsh[k0 + kp + 1];
            const int ka = k0 + kp;

            // S = fl( fl(A+B) - 2*C ): fmaf gives the single final rounding (2*C exact)
            float Xa0 = A0 + Ba;  float Sa0 = fmaf(-2.f, ca0, Xa0);
            if (Sa0 < best0) { best0 = Sa0; bi0 = ka; }
            float Xb0 = A0 + Bb;  float Sb0 = fmaf(-2.f, cb0, Xb0);
            if (Sb0 < best0) { best0 = Sb0; bi0 = ka + 1; }
            float Xa1 = A1 + Ba;  float Sa1 = fmaf(-2.f, ca1, Xa1);
            if (Sa1 < best1) { best1 = Sa1; bi1 = ka; }
            float Xb1 = A1 + Bb;  float Sb1 = fmaf(-2.f, cb1, Xb1);
            if (Sb1 < best1) { best1 = Sb1; bi1 = ka + 1; }
        }
    }

    // --- emit Zq = fl(z + fl(e - z)) (straight-through arithmetic) + loss partial ---
    float ls = 0.f;
    {
        const float* er0 = E + bi0 * DDIM;
        const float* er1 = E + bi1 * DDIM;
        float* o0 = out + zq_off + (size_t)b0 * CHW + hw0;
        float* o1 = out + zq_off + (size_t)b1 * CHW + hw1;
        #pragma unroll
        for (int d = 0; d < DDIM; d++) {
            float zlo, zhi; unpack2(zp[d], zlo, zhi);
            float q0 = __ldg(er0 + d);
            float q1 = __ldg(er1 + d);
            float t0 = q0 - zlo;
            float t1 = q1 - zhi;
            ls += t0 * t0;
            ls += t1 * t1;
            o0[(size_t)d * HW] = zlo + t0;
            o1[(size_t)d * HW] = zhi + t1;
        }
    }

    // --- deterministic block reduction ---
    #pragma unroll
    for (int off = 16; off; off >>= 1) ls += __shfl_down_sync(0xffffffffu, ls, off);
    int wid = tid >> 5, lane = tid & 31;
    if (lane == 0) red[wid] = ls;
    __syncthreads();
    if (tid == 0) {
        float t = 0.f;
        #pragma unroll
        for (int i = 0; i < 8; i++) t += red[i];
        g_blocksums[blockIdx.x] = t;
    }
}

__global__ void vq_loss_kernel(float* __restrict__ out)
{
    int t = threadIdx.x;  // 32 threads
    double s = 0.0;
    for (int i = t; i < NBLOCKS; i += 32) s += (double)g_blocksums[i];
    #pragma unroll
    for (int off = 16; off; off >>= 1) s += __shfl_down_sync(0xffffffffu, s, off);
    if (t == 0) out[0] = (float)(s * (1.25 / 8388608.0));
}

extern "C" void kernel_launch(void* const* d_in, const int* in_sizes, int n_in,
                              void* d_out, int out_size)
{
    const float* inp = (const float*)d_in[0];  // [32,64,64,64] fp32
    const float* E   = (const float*)d_in[1];  // [512,64] fp32
    float* out = (float*)d_out;

    int zq_off = (out_size > ZQ_ELEMS) ? (out_size - ZQ_ELEMS) : 0;

    const int smem_bytes = DDIM * KSTRIDE * 8 + KC * 4;  // 132096 + 2048 = 134144
    cudaFuncSetAttribute(vq_main_kernel, cudaFuncAttributeMaxDynamicSharedMemorySize, smem_bytes);

    vq_main_kernel<<<NBLOCKS, THREADS, smem_bytes>>>(inp, E, out, zq_off);
    if (zq_off >= 1) {
        vq_loss_kernel<<<1, 32>>>(out);
    }
}